// round 5
// baseline (speedup 1.0000x reference)
#include <cuda_runtime.h>

// Problem constants
#define HW2    65536          // 256*256 pixels
#define N_PIX  65536
#define BATCH  64
#define CH     3

// Scratch (allocation-free rule: __device__ globals)
__device__ float g_G[6 * N_PIX];      // raw covariance /B : g00,g01,g02,g11,g12,g22 (SoA planes)
__device__ float g_mats[27 * N_PIX];  // A(9), C(9), 8L(6: l00,l10,l11,l20,l21,l22), d(3)
__device__ float g_trsum;             // sum over pixels of trace(G_raw)

// ---------------------------------------------------------------------------
// Kernel 0: zero the trace accumulator (graph-capturable, deterministic)
// ---------------------------------------------------------------------------
__global__ void k_zero() { g_trsum = 0.0f; }

// ---------------------------------------------------------------------------
// Kernel 1: per-pixel covariance G = (1/64) sum_b s s^T  + trace reduction
// score_x layout: [B=64, C=3, H*W=65536]
// ---------------------------------------------------------------------------
__global__ __launch_bounds__(256) void k_covar(const float* __restrict__ s) {
    const int p = blockIdx.x * blockDim.x + threadIdx.x;
    float g00 = 0.f, g01 = 0.f, g02 = 0.f, g11 = 0.f, g12 = 0.f, g22 = 0.f;
    const float* sp = s + p;
#pragma unroll 4
    for (int b = 0; b < BATCH; ++b) {
        const float* base = sp + (size_t)b * (CH * HW2);
        float s0 = __ldg(base);
        float s1 = __ldg(base + HW2);
        float s2 = __ldg(base + 2 * HW2);
        g00 += s0 * s0; g01 += s0 * s1; g02 += s0 * s2;
        g11 += s1 * s1; g12 += s1 * s2; g22 += s2 * s2;
    }
    const float ib = 1.0f / 64.0f;
    g00 *= ib; g01 *= ib; g02 *= ib; g11 *= ib; g12 *= ib; g22 *= ib;

    g_G[0 * N_PIX + p] = g00;
    g_G[1 * N_PIX + p] = g01;
    g_G[2 * N_PIX + p] = g02;
    g_G[3 * N_PIX + p] = g11;
    g_G[4 * N_PIX + p] = g12;
    g_G[5 * N_PIX + p] = g22;

    // block-level trace reduction -> single atomicAdd per block
    float tr = g00 + g11 + g22;
#pragma unroll
    for (int o = 16; o > 0; o >>= 1)
        tr += __shfl_down_sync(0xffffffffu, tr, o);
    __shared__ float sh[8];
    const int lane = threadIdx.x & 31;
    const int w    = threadIdx.x >> 5;
    if (lane == 0) sh[w] = tr;
    __syncthreads();
    if (threadIdx.x == 0) {
        float acc = 0.f;
#pragma unroll
        for (int i = 0; i < 8; ++i) acc += sh[i];
        atomicAdd(&g_trsum, acc);
    }
}

// ---------------------------------------------------------------------------
// Kernel 2: per-pixel matrix prep.
//   norm  = (t0==1) ? mean_trace/3 * 4 : 1
//   alpha = 0.5*exp(-4.5*(1-t0))
//   G     = alpha*G/norm + (1-alpha)*0.25*I
//   A  = 8 * L * Ginv                  (drift_x = A r)
//   C  = 0.64 * G * Ginv               (drift_r -= C r)
//   8L                                 (drift_r -= 8L x)
//   d  = sqrt(1.28) * rowsum(L)        (diffusion_r, batch-independent)
// ---------------------------------------------------------------------------
__global__ __launch_bounds__(256) void k_prep(const float* __restrict__ t) {
    const int p = blockIdx.x * blockDim.x + threadIdx.x;

    const float t0 = __ldg(t);
    const float diag_mean = g_trsum / (65536.0f * 3.0f);
    const float norm  = (t0 == 1.0f) ? diag_mean * 4.0f : 1.0f;
    const float alpha = 0.5f * expf(-4.5f * (1.0f - t0));
    const float sa = alpha / norm;
    const float diag_add = (1.0f - alpha) * 0.25f;

    float g00 = g_G[0 * N_PIX + p] * sa + diag_add;
    float g01 = g_G[1 * N_PIX + p] * sa;
    float g02 = g_G[2 * N_PIX + p] * sa;
    float g11 = g_G[3 * N_PIX + p] * sa + diag_add;
    float g12 = g_G[4 * N_PIX + p] * sa;
    float g22 = g_G[5 * N_PIX + p] * sa + diag_add;

    // fp64 for inverse + cholesky (tiny op count; robust & close to exact)
    double a00 = g00, a01 = g01, a02 = g02, a11 = g11, a12 = g12, a22 = g22;
    double c00 = a11 * a22 - a12 * a12;
    double c01 = a02 * a12 - a01 * a22;
    double c02 = a01 * a12 - a02 * a11;
    double det = a00 * c00 + a01 * c01 + a02 * c02;
    double id  = 1.0 / det;
    double i00 = c00 * id;
    double i01 = c01 * id;
    double i02 = c02 * id;
    double i11 = (a00 * a22 - a02 * a02) * id;
    double i12 = (a01 * a02 - a00 * a12) * id;
    double i22 = (a00 * a11 - a01 * a01) * id;

    double l00 = sqrt(a00);
    double l10 = a01 / l00;
    double l20 = a02 / l00;
    double l11 = sqrt(a11 - l10 * l10);
    double l21 = (a12 - l20 * l10) / l11;
    double l22 = sqrt(a22 - l20 * l20 - l21 * l21);

    // A = 8 * L * Ginv   (Ginv rows: (i00,i01,i02),(i01,i11,i12),(i02,i12,i22))
    float A00 = (float)(8.0 * (l00 * i00));
    float A01 = (float)(8.0 * (l00 * i01));
    float A02 = (float)(8.0 * (l00 * i02));
    float A10 = (float)(8.0 * (l10 * i00 + l11 * i01));
    float A11 = (float)(8.0 * (l10 * i01 + l11 * i11));
    float A12 = (float)(8.0 * (l10 * i02 + l11 * i12));
    float A20 = (float)(8.0 * (l20 * i00 + l21 * i01 + l22 * i02));
    float A21 = (float)(8.0 * (l20 * i01 + l21 * i11 + l22 * i12));
    float A22 = (float)(8.0 * (l20 * i02 + l21 * i12 + l22 * i22));

    // C = 0.64 * G * Ginv  (faithful to reference's G @ (Ginv r); numerically ~0.64*I)
    float C00 = (float)(0.64 * (a00 * i00 + a01 * i01 + a02 * i02));
    float C01 = (float)(0.64 * (a00 * i01 + a01 * i11 + a02 * i12));
    float C02 = (float)(0.64 * (a00 * i02 + a01 * i12 + a02 * i22));
    float C10 = (float)(0.64 * (a01 * i00 + a11 * i01 + a12 * i02));
    float C11 = (float)(0.64 * (a01 * i01 + a11 * i11 + a12 * i12));
    float C12 = (float)(0.64 * (a01 * i02 + a11 * i12 + a12 * i22));
    float C20 = (float)(0.64 * (a02 * i00 + a12 * i01 + a22 * i02));
    float C21 = (float)(0.64 * (a02 * i01 + a12 * i11 + a22 * i12));
    float C22 = (float)(0.64 * (a02 * i02 + a12 * i12 + a22 * i22));

    const double bg = 1.1313708498984762;  // sqrt(2*8*0.08)
    float D0 = (float)(bg * l00);
    float D1 = (float)(bg * (l10 + l11));
    float D2 = (float)(bg * (l20 + l21 + l22));

    float* m = g_mats;
    m[ 0 * N_PIX + p] = A00; m[ 1 * N_PIX + p] = A01; m[ 2 * N_PIX + p] = A02;
    m[ 3 * N_PIX + p] = A10; m[ 4 * N_PIX + p] = A11; m[ 5 * N_PIX + p] = A12;
    m[ 6 * N_PIX + p] = A20; m[ 7 * N_PIX + p] = A21; m[ 8 * N_PIX + p] = A22;
    m[ 9 * N_PIX + p] = C00; m[10 * N_PIX + p] = C01; m[11 * N_PIX + p] = C02;
    m[12 * N_PIX + p] = C10; m[13 * N_PIX + p] = C11; m[14 * N_PIX + p] = C12;
    m[15 * N_PIX + p] = C20; m[16 * N_PIX + p] = C21; m[17 * N_PIX + p] = C22;
    m[18 * N_PIX + p] = (float)(8.0 * l00);
    m[19 * N_PIX + p] = (float)(8.0 * l10);
    m[20 * N_PIX + p] = (float)(8.0 * l11);
    m[21 * N_PIX + p] = (float)(8.0 * l20);
    m[22 * N_PIX + p] = (float)(8.0 * l21);
    m[23 * N_PIX + p] = (float)(8.0 * l22);
    m[24 * N_PIX + p] = D0;
    m[25 * N_PIX + p] = D1;
    m[26 * N_PIX + p] = D2;
}

// ---------------------------------------------------------------------------
// Kernel 3: streaming apply over (batch, pixel).
//   u  : [64, 6, HW2]  (x = ch 0..2, r = ch 3..5)
//   out: drift [64,6,HW2] then diffusion [64,6,HW2]
// Batch split x4: thread handles one pixel, 16 batches -> 56 warps/SM for MLP.
// ---------------------------------------------------------------------------
__global__ __launch_bounds__(256) void k_apply(const float* __restrict__ u,
                                               float* __restrict__ out) {
    const int idx = blockIdx.x * blockDim.x + threadIdx.x;  // 0..262143
    const int p   = idx & (N_PIX - 1);
    const int bq  = idx >> 16;  // 0..3

    const float* m = g_mats;
    const float A00 = m[ 0 * N_PIX + p], A01 = m[ 1 * N_PIX + p], A02 = m[ 2 * N_PIX + p];
    const float A10 = m[ 3 * N_PIX + p], A11 = m[ 4 * N_PIX + p], A12 = m[ 5 * N_PIX + p];
    const float A20 = m[ 6 * N_PIX + p], A21 = m[ 7 * N_PIX + p], A22 = m[ 8 * N_PIX + p];
    const float C00 = m[ 9 * N_PIX + p], C01 = m[10 * N_PIX + p], C02 = m[11 * N_PIX + p];
    const float C10 = m[12 * N_PIX + p], C11 = m[13 * N_PIX + p], C12 = m[14 * N_PIX + p];
    const float C20 = m[15 * N_PIX + p], C21 = m[16 * N_PIX + p], C22 = m[17 * N_PIX + p];
    const float L00 = m[18 * N_PIX + p];
    const float L10 = m[19 * N_PIX + p], L11 = m[20 * N_PIX + p];
    const float L20 = m[21 * N_PIX + p], L21 = m[22 * N_PIX + p], L22 = m[23 * N_PIX + p];
    const float D0  = m[24 * N_PIX + p], D1 = m[25 * N_PIX + p], D2 = m[26 * N_PIX + p];

    const size_t diff_off = (size_t)BATCH * 6 * HW2;  // 25165824

#pragma unroll 2
    for (int i = 0; i < 16; ++i) {
        const int b = bq * 16 + i;
        const float* ub = u + (size_t)b * (6 * HW2) + p;
        const float x0 = __ldg(ub);
        const float x1 = __ldg(ub + HW2);
        const float x2 = __ldg(ub + 2 * HW2);
        const float r0 = __ldg(ub + 3 * HW2);
        const float r1 = __ldg(ub + 4 * HW2);
        const float r2 = __ldg(ub + 5 * HW2);

        // drift_x = A r
        const float dx0 = A00 * r0 + A01 * r1 + A02 * r2;
        const float dx1 = A10 * r0 + A11 * r1 + A12 * r2;
        const float dx2 = A20 * r0 + A21 * r1 + A22 * r2;
        // drift_r = -(8L) x - C r
        const float dr0 = -(L00 * x0)                         - (C00 * r0 + C01 * r1 + C02 * r2);
        const float dr1 = -(L10 * x0 + L11 * x1)              - (C10 * r0 + C11 * r1 + C12 * r2);
        const float dr2 = -(L20 * x0 + L21 * x1 + L22 * x2)   - (C20 * r0 + C21 * r1 + C22 * r2);

        float* ob = out + (size_t)b * (6 * HW2) + p;
        ob[0 * HW2] = dx0;
        ob[1 * HW2] = dx1;
        ob[2 * HW2] = dx2;
        ob[3 * HW2] = dr0;
        ob[4 * HW2] = dr1;
        ob[5 * HW2] = dr2;

        float* db = ob + diff_off;
        db[0 * HW2] = 0.0f;
        db[1 * HW2] = 0.0f;
        db[2 * HW2] = 0.0f;
        db[3 * HW2] = D0;
        db[4 * HW2] = D1;
        db[5 * HW2] = D2;
    }
}

// ---------------------------------------------------------------------------
extern "C" void kernel_launch(void* const* d_in, const int* in_sizes, int n_in,
                              void* d_out, int out_size) {
    const float* u  = (const float*)d_in[0];   // [64, 6, 256, 256]
    const float* sx = (const float*)d_in[1];   // [64, 3, 256, 256]
    const float* t  = (const float*)d_in[2];   // [64]
    float* out = (float*)d_out;                // drift(25165824) + diffusion(25165824)

    k_zero<<<1, 1>>>();
    k_covar<<<N_PIX / 256, 256>>>(sx);
    k_prep<<<N_PIX / 256, 256>>>(t);
    k_apply<<<(N_PIX * 4) / 256, 256>>>(u, out);
}

// round 6
// speedup vs baseline: 1.3962x; 1.3962x over previous
#include <cuda_runtime.h>

// Problem constants
#define HW2    65536          // 256*256 pixels
#define N_PIX  65536
#define BATCH  64
#define CH     3
#define NBLK_COV 256          // k_covar grid (65536/256)

// Scratch (allocation-free rule: __device__ globals)
__device__ float g_G[6 * N_PIX];        // raw covariance /B : g00,g01,g02,g11,g12,g22 (SoA planes)
__device__ float g_mats[27 * N_PIX];    // A(9), C(9), 8L(6), d(3)
__device__ float g_partial[NBLK_COV];   // per-block trace partial sums

// ---------------------------------------------------------------------------
// Kernel 1: per-pixel covariance G = (1/64) sum_b s s^T  + per-block trace partial
// score_x layout: [B=64, C=3, H*W=65536]
// ---------------------------------------------------------------------------
__global__ __launch_bounds__(256) void k_covar(const float* __restrict__ s) {
    const int p = blockIdx.x * blockDim.x + threadIdx.x;
    float g00 = 0.f, g01 = 0.f, g02 = 0.f, g11 = 0.f, g12 = 0.f, g22 = 0.f;
    const float* sp = s + p;
#pragma unroll 4
    for (int b = 0; b < BATCH; ++b) {
        const float* base = sp + (size_t)b * (CH * HW2);
        float s0 = __ldcs(base);
        float s1 = __ldcs(base + HW2);
        float s2 = __ldcs(base + 2 * HW2);
        g00 += s0 * s0; g01 += s0 * s1; g02 += s0 * s2;
        g11 += s1 * s1; g12 += s1 * s2; g22 += s2 * s2;
    }
    const float ib = 1.0f / 64.0f;
    g00 *= ib; g01 *= ib; g02 *= ib; g11 *= ib; g12 *= ib; g22 *= ib;

    g_G[0 * N_PIX + p] = g00;
    g_G[1 * N_PIX + p] = g01;
    g_G[2 * N_PIX + p] = g02;
    g_G[3 * N_PIX + p] = g11;
    g_G[4 * N_PIX + p] = g12;
    g_G[5 * N_PIX + p] = g22;

    // block-level trace reduction -> one partial per block (no atomics, no zero-kernel)
    float tr = g00 + g11 + g22;
#pragma unroll
    for (int o = 16; o > 0; o >>= 1)
        tr += __shfl_down_sync(0xffffffffu, tr, o);
    __shared__ float sh[8];
    const int lane = threadIdx.x & 31;
    const int w    = threadIdx.x >> 5;
    if (lane == 0) sh[w] = tr;
    __syncthreads();
    if (threadIdx.x == 0) {
        float acc = 0.f;
#pragma unroll
        for (int i = 0; i < 8; ++i) acc += sh[i];
        g_partial[blockIdx.x] = acc;
    }
}

// ---------------------------------------------------------------------------
// Kernel 2: per-pixel matrix prep (fp32 — G is well conditioned, diag >= 0.125).
//   Each block redundantly reduces the 256 trace partials (L2-resident).
//   norm  = (t0==1) ? mean_trace/3 * 4 : 1
//   alpha = 0.5*exp(-4.5*(1-t0))
//   G     = alpha*G/norm + (1-alpha)*0.25*I
//   A = 8*L*Ginv ; C = 0.64*G*Ginv ; 8L ; d = sqrt(1.28)*rowsum(L)
// ---------------------------------------------------------------------------
__global__ __launch_bounds__(256) void k_prep(const float* __restrict__ t) {
    // in-block reduction of the 256 partials, broadcast via shared
    __shared__ float sh_sum;
    {
        float v = g_partial[threadIdx.x];
#pragma unroll
        for (int o = 16; o > 0; o >>= 1)
            v += __shfl_down_sync(0xffffffffu, v, o);
        __shared__ float sh[8];
        const int lane = threadIdx.x & 31;
        const int w    = threadIdx.x >> 5;
        if (lane == 0) sh[w] = v;
        __syncthreads();
        if (threadIdx.x == 0) {
            float acc = 0.f;
#pragma unroll
            for (int i = 0; i < 8; ++i) acc += sh[i];
            sh_sum = acc;
        }
        __syncthreads();
    }

    const int p = blockIdx.x * blockDim.x + threadIdx.x;
    const float t0 = __ldg(t);
    const float diag_mean = sh_sum / (65536.0f * 3.0f);
    const float norm  = (t0 == 1.0f) ? diag_mean * 4.0f : 1.0f;
    const float alpha = 0.5f * __expf(-4.5f * (1.0f - t0));
    const float sa = alpha / norm;
    const float diag_add = (1.0f - alpha) * 0.25f;

    const float a00 = g_G[0 * N_PIX + p] * sa + diag_add;
    const float a01 = g_G[1 * N_PIX + p] * sa;
    const float a02 = g_G[2 * N_PIX + p] * sa;
    const float a11 = g_G[3 * N_PIX + p] * sa + diag_add;
    const float a12 = g_G[4 * N_PIX + p] * sa;
    const float a22 = g_G[5 * N_PIX + p] * sa + diag_add;

    // adjugate inverse (fp32)
    const float c00 = a11 * a22 - a12 * a12;
    const float c01 = a02 * a12 - a01 * a22;
    const float c02 = a01 * a12 - a02 * a11;
    const float det = a00 * c00 + a01 * c01 + a02 * c02;
    const float id  = 1.0f / det;
    const float i00 = c00 * id;
    const float i01 = c01 * id;
    const float i02 = c02 * id;
    const float i11 = (a00 * a22 - a02 * a02) * id;
    const float i12 = (a01 * a02 - a00 * a12) * id;
    const float i22 = (a00 * a11 - a01 * a01) * id;

    // Cholesky (fp32)
    const float l00 = sqrtf(a00);
    const float il00 = 1.0f / l00;
    const float l10 = a01 * il00;
    const float l20 = a02 * il00;
    const float l11 = sqrtf(a11 - l10 * l10);
    const float l21 = (a12 - l20 * l10) / l11;
    const float l22 = sqrtf(a22 - l20 * l20 - l21 * l21);

    // A = 8 * L * Ginv
    const float A00 = 8.0f * (l00 * i00);
    const float A01 = 8.0f * (l00 * i01);
    const float A02 = 8.0f * (l00 * i02);
    const float A10 = 8.0f * (l10 * i00 + l11 * i01);
    const float A11 = 8.0f * (l10 * i01 + l11 * i11);
    const float A12 = 8.0f * (l10 * i02 + l11 * i12);
    const float A20 = 8.0f * (l20 * i00 + l21 * i01 + l22 * i02);
    const float A21 = 8.0f * (l20 * i01 + l21 * i11 + l22 * i12);
    const float A22 = 8.0f * (l20 * i02 + l21 * i12 + l22 * i22);

    // C = 0.64 * G * Ginv (faithful to reference's G @ (Ginv r))
    const float C00 = 0.64f * (a00 * i00 + a01 * i01 + a02 * i02);
    const float C01 = 0.64f * (a00 * i01 + a01 * i11 + a02 * i12);
    const float C02 = 0.64f * (a00 * i02 + a01 * i12 + a02 * i22);
    const float C10 = 0.64f * (a01 * i00 + a11 * i01 + a12 * i02);
    const float C11 = 0.64f * (a01 * i01 + a11 * i11 + a12 * i12);
    const float C12 = 0.64f * (a01 * i02 + a11 * i12 + a12 * i22);
    const float C20 = 0.64f * (a02 * i00 + a12 * i01 + a22 * i02);
    const float C21 = 0.64f * (a02 * i01 + a12 * i11 + a22 * i12);
    const float C22 = 0.64f * (a02 * i02 + a12 * i12 + a22 * i22);

    const float bg = 1.1313708498984762f;  // sqrt(2*8*0.08)
    const float D0 = bg * l00;
    const float D1 = bg * (l10 + l11);
    const float D2 = bg * (l20 + l21 + l22);

    float* m = g_mats;
    m[ 0 * N_PIX + p] = A00; m[ 1 * N_PIX + p] = A01; m[ 2 * N_PIX + p] = A02;
    m[ 3 * N_PIX + p] = A10; m[ 4 * N_PIX + p] = A11; m[ 5 * N_PIX + p] = A12;
    m[ 6 * N_PIX + p] = A20; m[ 7 * N_PIX + p] = A21; m[ 8 * N_PIX + p] = A22;
    m[ 9 * N_PIX + p] = C00; m[10 * N_PIX + p] = C01; m[11 * N_PIX + p] = C02;
    m[12 * N_PIX + p] = C10; m[13 * N_PIX + p] = C11; m[14 * N_PIX + p] = C12;
    m[15 * N_PIX + p] = C20; m[16 * N_PIX + p] = C21; m[17 * N_PIX + p] = C22;
    m[18 * N_PIX + p] = 8.0f * l00;
    m[19 * N_PIX + p] = 8.0f * l10;
    m[20 * N_PIX + p] = 8.0f * l11;
    m[21 * N_PIX + p] = 8.0f * l20;
    m[22 * N_PIX + p] = 8.0f * l21;
    m[23 * N_PIX + p] = 8.0f * l22;
    m[24 * N_PIX + p] = D0;
    m[25 * N_PIX + p] = D1;
    m[26 * N_PIX + p] = D2;
}

// ---------------------------------------------------------------------------
// Kernel 3: streaming apply over (batch, pixel).
//   u  : [64, 6, HW2]  (x = ch 0..2, r = ch 3..5)
//   out: drift [64,6,HW2] then diffusion [64,6,HW2]
// Batch split x8: 2048 blocks (~13.8/SM, good wave balance). Streaming hints on
// read-once u and write-once out; matrices (7MB) stay L2-resident via __ldg.
// ---------------------------------------------------------------------------
__global__ __launch_bounds__(256) void k_apply(const float* __restrict__ u,
                                               float* __restrict__ out) {
    const int idx = blockIdx.x * blockDim.x + threadIdx.x;  // 0..524287
    const int p   = idx & (N_PIX - 1);
    const int bq  = idx >> 16;  // 0..7

    const float* m = g_mats;
    const float A00 = __ldg(m +  0 * N_PIX + p), A01 = __ldg(m +  1 * N_PIX + p), A02 = __ldg(m +  2 * N_PIX + p);
    const float A10 = __ldg(m +  3 * N_PIX + p), A11 = __ldg(m +  4 * N_PIX + p), A12 = __ldg(m +  5 * N_PIX + p);
    const float A20 = __ldg(m +  6 * N_PIX + p), A21 = __ldg(m +  7 * N_PIX + p), A22 = __ldg(m +  8 * N_PIX + p);
    const float C00 = __ldg(m +  9 * N_PIX + p), C01 = __ldg(m + 10 * N_PIX + p), C02 = __ldg(m + 11 * N_PIX + p);
    const float C10 = __ldg(m + 12 * N_PIX + p), C11 = __ldg(m + 13 * N_PIX + p), C12 = __ldg(m + 14 * N_PIX + p);
    const float C20 = __ldg(m + 15 * N_PIX + p), C21 = __ldg(m + 16 * N_PIX + p), C22 = __ldg(m + 17 * N_PIX + p);
    const float L00 = __ldg(m + 18 * N_PIX + p);
    const float L10 = __ldg(m + 19 * N_PIX + p), L11 = __ldg(m + 20 * N_PIX + p);
    const float L20 = __ldg(m + 21 * N_PIX + p), L21 = __ldg(m + 22 * N_PIX + p), L22 = __ldg(m + 23 * N_PIX + p);
    const float D0  = __ldg(m + 24 * N_PIX + p), D1 = __ldg(m + 25 * N_PIX + p), D2 = __ldg(m + 26 * N_PIX + p);

    const size_t diff_off = (size_t)BATCH * 6 * HW2;  // 25165824

#pragma unroll 2
    for (int i = 0; i < 8; ++i) {
        const int b = bq * 8 + i;
        const float* ub = u + (size_t)b * (6 * HW2) + p;
        const float x0 = __ldcs(ub);
        const float x1 = __ldcs(ub + HW2);
        const float x2 = __ldcs(ub + 2 * HW2);
        const float r0 = __ldcs(ub + 3 * HW2);
        const float r1 = __ldcs(ub + 4 * HW2);
        const float r2 = __ldcs(ub + 5 * HW2);

        // drift_x = A r
        const float dx0 = A00 * r0 + A01 * r1 + A02 * r2;
        const float dx1 = A10 * r0 + A11 * r1 + A12 * r2;
        const float dx2 = A20 * r0 + A21 * r1 + A22 * r2;
        // drift_r = -(8L) x - C r
        const float dr0 = -(L00 * x0)                       - (C00 * r0 + C01 * r1 + C02 * r2);
        const float dr1 = -(L10 * x0 + L11 * x1)            - (C10 * r0 + C11 * r1 + C12 * r2);
        const float dr2 = -(L20 * x0 + L21 * x1 + L22 * x2) - (C20 * r0 + C21 * r1 + C22 * r2);

        float* ob = out + (size_t)b * (6 * HW2) + p;
        __stcs(ob + 0 * HW2, dx0);
        __stcs(ob + 1 * HW2, dx1);
        __stcs(ob + 2 * HW2, dx2);
        __stcs(ob + 3 * HW2, dr0);
        __stcs(ob + 4 * HW2, dr1);
        __stcs(ob + 5 * HW2, dr2);

        float* db = ob + diff_off;
        __stcs(db + 0 * HW2, 0.0f);
        __stcs(db + 1 * HW2, 0.0f);
        __stcs(db + 2 * HW2, 0.0f);
        __stcs(db + 3 * HW2, D0);
        __stcs(db + 4 * HW2, D1);
        __stcs(db + 5 * HW2, D2);
    }
}

// ---------------------------------------------------------------------------
extern "C" void kernel_launch(void* const* d_in, const int* in_sizes, int n_in,
                              void* d_out, int out_size) {
    const float* u  = (const float*)d_in[0];   // [64, 6, 256, 256]
    const float* sx = (const float*)d_in[1];   // [64, 3, 256, 256]
    const float* t  = (const float*)d_in[2];   // [64]
    float* out = (float*)d_out;                // drift(25165824) + diffusion(25165824)

    k_covar<<<NBLK_COV, 256>>>(sx);
    k_prep<<<N_PIX / 256, 256>>>(t);
    k_apply<<<(N_PIX * 8) / 256, 256>>>(u, out);
}

// round 7
// speedup vs baseline: 1.4012x; 1.0035x over previous
#include <cuda_runtime.h>

// Problem constants
#define HW2        65536      // 256*256 pixels
#define N_PIX      65536
#define N_Q        16384      // pixel quads (float4 granularity)
#define BATCH      64
#define COV_SPLIT  8          // batch split in k_covar (8 batches per thread)
#define NBLK_COV   512        // (N_Q * COV_SPLIT) / 256

// Scratch (allocation-free rule: __device__ globals)
__device__ float g_Gpart[COV_SPLIT * 6 * N_PIX]; // partial covariances, [split][plane][pix]
__device__ float g_mats[27 * N_PIX];             // A(9), C(9), 8L(6), d(3) — plane-major
__device__ float g_partial[NBLK_COV];            // per-block trace partial sums

// ---- float4 helpers --------------------------------------------------------
__device__ __forceinline__ float4 f4mul(float4 a, float4 b) {
    return make_float4(a.x * b.x, a.y * b.y, a.z * b.z, a.w * b.w);
}
__device__ __forceinline__ float4 f4fma(float4 a, float4 b, float4 c) {
    return make_float4(fmaf(a.x, b.x, c.x), fmaf(a.y, b.y, c.y),
                       fmaf(a.z, b.z, c.z), fmaf(a.w, b.w, c.w));
}
__device__ __forceinline__ float4 f4neg(float4 a) {
    return make_float4(-a.x, -a.y, -a.z, -a.w);
}
__device__ __forceinline__ float4 f4scale(float4 a, float s) {
    return make_float4(a.x * s, a.y * s, a.z * s, a.w * s);
}

// ---------------------------------------------------------------------------
// Kernel 1: partial per-pixel covariance, float4 pixels, batch split x8.
// score_x: [64, 3, 65536] floats = [64, 3, 16384] float4.
// Each thread: pixel-quad q, batches [bq*8, bq*8+8) -> partial 6-plane cov.
// ---------------------------------------------------------------------------
__global__ __launch_bounds__(256) void k_covar(const float4* __restrict__ s4) {
    const int idx = blockIdx.x * blockDim.x + threadIdx.x;  // 0..131071
    const int q   = idx & (N_Q - 1);
    const int bq  = idx >> 14;                               // 0..7

    float4 a00 = make_float4(0.f, 0.f, 0.f, 0.f), a01 = a00, a02 = a00;
    float4 a11 = a00, a12 = a00, a22 = a00;

#pragma unroll
    for (int i = 0; i < 8; ++i) {
        const int b = bq * 8 + i;
        const float4* base = s4 + (size_t)b * (3 * N_Q) + q;
        const float4 s0 = __ldcs(base);
        const float4 s1 = __ldcs(base + N_Q);
        const float4 s2 = __ldcs(base + 2 * N_Q);
        a00 = f4fma(s0, s0, a00); a01 = f4fma(s0, s1, a01); a02 = f4fma(s0, s2, a02);
        a11 = f4fma(s1, s1, a11); a12 = f4fma(s1, s2, a12); a22 = f4fma(s2, s2, a22);
    }
    const float ib = 1.0f / 64.0f;
    a00 = f4scale(a00, ib); a01 = f4scale(a01, ib); a02 = f4scale(a02, ib);
    a11 = f4scale(a11, ib); a12 = f4scale(a12, ib); a22 = f4scale(a22, ib);

    float4* gp = (float4*)g_Gpart + (size_t)bq * (6 * N_Q) + q;
    gp[0 * N_Q] = a00; gp[1 * N_Q] = a01; gp[2 * N_Q] = a02;
    gp[3 * N_Q] = a11; gp[4 * N_Q] = a12; gp[5 * N_Q] = a22;

    // trace partial (linear in batch -> partial sums compose)
    float tr = (a00.x + a00.y + a00.z + a00.w)
             + (a11.x + a11.y + a11.z + a11.w)
             + (a22.x + a22.y + a22.z + a22.w);
#pragma unroll
    for (int o = 16; o > 0; o >>= 1)
        tr += __shfl_down_sync(0xffffffffu, tr, o);
    __shared__ float sh[8];
    const int lane = threadIdx.x & 31;
    const int w    = threadIdx.x >> 5;
    if (lane == 0) sh[w] = tr;
    __syncthreads();
    if (threadIdx.x == 0) {
        float acc = 0.f;
#pragma unroll
        for (int i = 0; i < 8; ++i) acc += sh[i];
        g_partial[blockIdx.x] = acc;
    }
}

// ---------------------------------------------------------------------------
// Kernel 2: reduce covariance partials, per-pixel matrix prep (fp32).
// ---------------------------------------------------------------------------
__global__ __launch_bounds__(256) void k_prep(const float* __restrict__ t) {
    // reduce 512 trace partials redundantly per block
    __shared__ float sh_sum;
    {
        float v = g_partial[threadIdx.x] + g_partial[threadIdx.x + 256];
#pragma unroll
        for (int o = 16; o > 0; o >>= 1)
            v += __shfl_down_sync(0xffffffffu, v, o);
        __shared__ float sh[8];
        const int lane = threadIdx.x & 31;
        const int w    = threadIdx.x >> 5;
        if (lane == 0) sh[w] = v;
        __syncthreads();
        if (threadIdx.x == 0) {
            float acc = 0.f;
#pragma unroll
            for (int i = 0; i < 8; ++i) acc += sh[i];
            sh_sum = acc;
        }
        __syncthreads();
    }

    const int p = blockIdx.x * blockDim.x + threadIdx.x;

    // reduce the 8 covariance partials for this pixel (48 coalesced loads)
    float g00 = 0.f, g01 = 0.f, g02 = 0.f, g11 = 0.f, g12 = 0.f, g22 = 0.f;
#pragma unroll
    for (int k = 0; k < COV_SPLIT; ++k) {
        const float* gp = g_Gpart + (size_t)k * (6 * N_PIX) + p;
        g00 += gp[0 * N_PIX]; g01 += gp[1 * N_PIX]; g02 += gp[2 * N_PIX];
        g11 += gp[3 * N_PIX]; g12 += gp[4 * N_PIX]; g22 += gp[5 * N_PIX];
    }

    const float t0 = __ldg(t);
    const float diag_mean = sh_sum / (65536.0f * 3.0f);
    const float norm  = (t0 == 1.0f) ? diag_mean * 4.0f : 1.0f;
    const float alpha = 0.5f * __expf(-4.5f * (1.0f - t0));
    const float sa = alpha / norm;
    const float diag_add = (1.0f - alpha) * 0.25f;

    const float a00 = g00 * sa + diag_add;
    const float a01 = g01 * sa;
    const float a02 = g02 * sa;
    const float a11 = g11 * sa + diag_add;
    const float a12 = g12 * sa;
    const float a22 = g22 * sa + diag_add;

    // adjugate inverse (fp32)
    const float c00 = a11 * a22 - a12 * a12;
    const float c01 = a02 * a12 - a01 * a22;
    const float c02 = a01 * a12 - a02 * a11;
    const float det = a00 * c00 + a01 * c01 + a02 * c02;
    const float id  = 1.0f / det;
    const float i00 = c00 * id;
    const float i01 = c01 * id;
    const float i02 = c02 * id;
    const float i11 = (a00 * a22 - a02 * a02) * id;
    const float i12 = (a01 * a02 - a00 * a12) * id;
    const float i22 = (a00 * a11 - a01 * a01) * id;

    // Cholesky (fp32)
    const float l00 = sqrtf(a00);
    const float il00 = 1.0f / l00;
    const float l10 = a01 * il00;
    const float l20 = a02 * il00;
    const float l11 = sqrtf(a11 - l10 * l10);
    const float l21 = (a12 - l20 * l10) / l11;
    const float l22 = sqrtf(a22 - l20 * l20 - l21 * l21);

    // A = 8 * L * Ginv
    const float A00 = 8.0f * (l00 * i00);
    const float A01 = 8.0f * (l00 * i01);
    const float A02 = 8.0f * (l00 * i02);
    const float A10 = 8.0f * (l10 * i00 + l11 * i01);
    const float A11 = 8.0f * (l10 * i01 + l11 * i11);
    const float A12 = 8.0f * (l10 * i02 + l11 * i12);
    const float A20 = 8.0f * (l20 * i00 + l21 * i01 + l22 * i02);
    const float A21 = 8.0f * (l20 * i01 + l21 * i11 + l22 * i12);
    const float A22 = 8.0f * (l20 * i02 + l21 * i12 + l22 * i22);

    // C = 0.64 * G * Ginv (faithful to reference's G @ (Ginv r))
    const float C00 = 0.64f * (a00 * i00 + a01 * i01 + a02 * i02);
    const float C01 = 0.64f * (a00 * i01 + a01 * i11 + a02 * i12);
    const float C02 = 0.64f * (a00 * i02 + a01 * i12 + a02 * i22);
    const float C10 = 0.64f * (a01 * i00 + a11 * i01 + a12 * i02);
    const float C11 = 0.64f * (a01 * i01 + a11 * i11 + a12 * i12);
    const float C12 = 0.64f * (a01 * i02 + a11 * i12 + a12 * i22);
    const float C20 = 0.64f * (a02 * i00 + a12 * i01 + a22 * i02);
    const float C21 = 0.64f * (a02 * i01 + a12 * i11 + a22 * i12);
    const float C22 = 0.64f * (a02 * i02 + a12 * i12 + a22 * i22);

    const float bg = 1.1313708498984762f;  // sqrt(2*8*0.08)

    float* m = g_mats;
    m[ 0 * N_PIX + p] = A00; m[ 1 * N_PIX + p] = A01; m[ 2 * N_PIX + p] = A02;
    m[ 3 * N_PIX + p] = A10; m[ 4 * N_PIX + p] = A11; m[ 5 * N_PIX + p] = A12;
    m[ 6 * N_PIX + p] = A20; m[ 7 * N_PIX + p] = A21; m[ 8 * N_PIX + p] = A22;
    m[ 9 * N_PIX + p] = C00; m[10 * N_PIX + p] = C01; m[11 * N_PIX + p] = C02;
    m[12 * N_PIX + p] = C10; m[13 * N_PIX + p] = C11; m[14 * N_PIX + p] = C12;
    m[15 * N_PIX + p] = C20; m[16 * N_PIX + p] = C21; m[17 * N_PIX + p] = C22;
    m[18 * N_PIX + p] = 8.0f * l00;
    m[19 * N_PIX + p] = 8.0f * l10;
    m[20 * N_PIX + p] = 8.0f * l11;
    m[21 * N_PIX + p] = 8.0f * l20;
    m[22 * N_PIX + p] = 8.0f * l21;
    m[23 * N_PIX + p] = 8.0f * l22;
    m[24 * N_PIX + p] = bg * l00;
    m[25 * N_PIX + p] = bg * (l10 + l11);
    m[26 * N_PIX + p] = bg * (l20 + l21 + l22);
}

// ---------------------------------------------------------------------------
// Kernel 3: streaming apply, float4 pixel-quads, 4 batches per thread.
//   u  : [64, 6, 16384] float4
//   out: drift [64,6,16384] f4 then diffusion [64,6,16384] f4
// 262144 threads / 1024 blocks. Matrices read once per thread (L2-resident).
// ---------------------------------------------------------------------------
__global__ __launch_bounds__(256) void k_apply(const float4* __restrict__ u4,
                                               float4* __restrict__ out4) {
    const int idx = blockIdx.x * blockDim.x + threadIdx.x;  // 0..262143
    const int q   = idx & (N_Q - 1);
    const int bq  = idx >> 14;  // 0..15

    const float4* m4 = (const float4*)g_mats;
    const float4 A00 = __ldg(m4 +  0 * N_Q + q), A01 = __ldg(m4 +  1 * N_Q + q), A02 = __ldg(m4 +  2 * N_Q + q);
    const float4 A10 = __ldg(m4 +  3 * N_Q + q), A11 = __ldg(m4 +  4 * N_Q + q), A12 = __ldg(m4 +  5 * N_Q + q);
    const float4 A20 = __ldg(m4 +  6 * N_Q + q), A21 = __ldg(m4 +  7 * N_Q + q), A22 = __ldg(m4 +  8 * N_Q + q);
    const float4 C00 = __ldg(m4 +  9 * N_Q + q), C01 = __ldg(m4 + 10 * N_Q + q), C02 = __ldg(m4 + 11 * N_Q + q);
    const float4 C10 = __ldg(m4 + 12 * N_Q + q), C11 = __ldg(m4 + 13 * N_Q + q), C12 = __ldg(m4 + 14 * N_Q + q);
    const float4 C20 = __ldg(m4 + 15 * N_Q + q), C21 = __ldg(m4 + 16 * N_Q + q), C22 = __ldg(m4 + 17 * N_Q + q);
    const float4 L00 = __ldg(m4 + 18 * N_Q + q);
    const float4 L10 = __ldg(m4 + 19 * N_Q + q), L11 = __ldg(m4 + 20 * N_Q + q);
    const float4 L20 = __ldg(m4 + 21 * N_Q + q), L21 = __ldg(m4 + 22 * N_Q + q), L22 = __ldg(m4 + 23 * N_Q + q);
    const float4 D0  = __ldg(m4 + 24 * N_Q + q), D1 = __ldg(m4 + 25 * N_Q + q), D2 = __ldg(m4 + 26 * N_Q + q);

    const size_t diff_off = (size_t)BATCH * 6 * N_Q;  // 6291456 float4
    const float4 zero = make_float4(0.f, 0.f, 0.f, 0.f);

#pragma unroll
    for (int i = 0; i < 4; ++i) {
        const int b = bq * 4 + i;
        const float4* ub = u4 + (size_t)b * (6 * N_Q) + q;
        const float4 x0 = __ldcs(ub);
        const float4 x1 = __ldcs(ub + N_Q);
        const float4 x2 = __ldcs(ub + 2 * N_Q);
        const float4 r0 = __ldcs(ub + 3 * N_Q);
        const float4 r1 = __ldcs(ub + 4 * N_Q);
        const float4 r2 = __ldcs(ub + 5 * N_Q);

        // drift_x = A r
        const float4 dx0 = f4fma(A02, r2, f4fma(A01, r1, f4mul(A00, r0)));
        const float4 dx1 = f4fma(A12, r2, f4fma(A11, r1, f4mul(A10, r0)));
        const float4 dx2 = f4fma(A22, r2, f4fma(A21, r1, f4mul(A20, r0)));
        // drift_r = -( (8L) x + C r )
        const float4 dr0 = f4neg(f4fma(C02, r2, f4fma(C01, r1, f4fma(C00, r0,
                              f4mul(L00, x0)))));
        const float4 dr1 = f4neg(f4fma(C12, r2, f4fma(C11, r1, f4fma(C10, r0,
                              f4fma(L11, x1, f4mul(L10, x0))))));
        const float4 dr2 = f4neg(f4fma(C22, r2, f4fma(C21, r1, f4fma(C20, r0,
                              f4fma(L22, x2, f4fma(L21, x1, f4mul(L20, x0)))))));

        float4* ob = out4 + (size_t)b * (6 * N_Q) + q;
        __stcs(ob + 0 * N_Q, dx0);
        __stcs(ob + 1 * N_Q, dx1);
        __stcs(ob + 2 * N_Q, dx2);
        __stcs(ob + 3 * N_Q, dr0);
        __stcs(ob + 4 * N_Q, dr1);
        __stcs(ob + 5 * N_Q, dr2);

        float4* db = ob + diff_off;
        __stcs(db + 0 * N_Q, zero);
        __stcs(db + 1 * N_Q, zero);
        __stcs(db + 2 * N_Q, zero);
        __stcs(db + 3 * N_Q, D0);
        __stcs(db + 4 * N_Q, D1);
        __stcs(db + 5 * N_Q, D2);
    }
}

// ---------------------------------------------------------------------------
extern "C" void kernel_launch(void* const* d_in, const int* in_sizes, int n_in,
                              void* d_out, int out_size) {
    const float4* u4 = (const float4*)d_in[0];   // [64, 6, 256, 256]
    const float4* s4 = (const float4*)d_in[1];   // [64, 3, 256, 256]
    const float*  t  = (const float*)d_in[2];    // [64]
    float4* out4 = (float4*)d_out;               // drift + diffusion

    k_covar<<<NBLK_COV, 256>>>(s4);
    k_prep<<<N_PIX / 256, 256>>>(t);
    k_apply<<<(N_Q * 16) / 256, 256>>>(u4, out4);
}

// round 8
// speedup vs baseline: 1.5742x; 1.1235x over previous
#include <cuda_runtime.h>

// Problem constants
#define HW2        65536      // 256*256 pixels
#define N_PIX      65536
#define N_Q        16384      // pixel quads (float4 granularity)
#define BATCH      64
#define NBLK_COV   512        // 16384 quads / 32 per block

// Scratch (allocation-free rule: __device__ globals)
__device__ float g_G[6 * N_PIX];       // covariance planes g00,g01,g02,g11,g12,g22
__device__ float g_mats[18 * N_PIX];   // A(9), 8L(6), d(3) — plane-major
__device__ float g_partial[NBLK_COV];  // per-block trace partial sums

// ---- float4 helpers --------------------------------------------------------
__device__ __forceinline__ float4 f4mul(float4 a, float4 b) {
    return make_float4(a.x * b.x, a.y * b.y, a.z * b.z, a.w * b.w);
}
__device__ __forceinline__ float4 f4fma(float4 a, float4 b, float4 c) {
    return make_float4(fmaf(a.x, b.x, c.x), fmaf(a.y, b.y, c.y),
                       fmaf(a.z, b.z, c.z), fmaf(a.w, b.w, c.w));
}
__device__ __forceinline__ float4 f4neg(float4 a) {
    return make_float4(-a.x, -a.y, -a.z, -a.w);
}
__device__ __forceinline__ float4 f4add(float4 a, float4 b) {
    return make_float4(a.x + b.x, a.y + b.y, a.z + b.z, a.w + b.w);
}
__device__ __forceinline__ float4 f4scale(float4 a, float s) {
    return make_float4(a.x * s, a.y * s, a.z * s, a.w * s);
}

// ---------------------------------------------------------------------------
// Kernel 1: per-pixel covariance with IN-BLOCK batch-split reduction.
// Block = 8 warps; warp w accumulates batches [8w, 8w+8) for the block's 32
// pixel-quads; shared-memory reduction collapses the 8 warp partials.
// No partial-covariance DRAM traffic.
// ---------------------------------------------------------------------------
__global__ __launch_bounds__(256) void k_covar(const float4* __restrict__ s4) {
    const int lane = threadIdx.x & 31;
    const int w    = threadIdx.x >> 5;           // warp id = batch split 0..7
    const int q    = blockIdx.x * 32 + lane;     // pixel quad

    float4 a0 = make_float4(0.f, 0.f, 0.f, 0.f);
    float4 a1 = a0, a2 = a0, a3 = a0, a4 = a0, a5 = a0;

#pragma unroll
    for (int i = 0; i < 8; ++i) {
        const int b = w * 8 + i;
        const float4* base = s4 + (size_t)b * (3 * N_Q) + q;
        const float4 s0 = __ldcs(base);
        const float4 s1 = __ldcs(base + N_Q);
        const float4 s2 = __ldcs(base + 2 * N_Q);
        a0 = f4fma(s0, s0, a0); a1 = f4fma(s0, s1, a1); a2 = f4fma(s0, s2, a2);
        a3 = f4fma(s1, s1, a3); a4 = f4fma(s1, s2, a4); a5 = f4fma(s2, s2, a5);
    }

    __shared__ float4 sh[6][8][32];              // 24 KB
    sh[0][w][lane] = a0; sh[1][w][lane] = a1; sh[2][w][lane] = a2;
    sh[3][w][lane] = a3; sh[4][w][lane] = a4; sh[5][w][lane] = a5;
    __syncthreads();

    // threads 0..191: (plane, quad_local) — sum the 8 warp partials
    float tr = 0.f;
    const int t = threadIdx.x;
    if (t < 192) {
        const int pl = t >> 5;
        const int ql = t & 31;
        float4 acc = sh[pl][0][ql];
#pragma unroll
        for (int ww = 1; ww < 8; ++ww) acc = f4add(acc, sh[pl][ww][ql]);
        acc = f4scale(acc, 1.0f / 64.0f);
        ((float4*)g_G)[(size_t)pl * N_Q + blockIdx.x * 32 + ql] = acc;
        if (pl == 0 || pl == 3 || pl == 5)
            tr = acc.x + acc.y + acc.z + acc.w;
    }

    // block reduce trace contributions -> one partial per block
#pragma unroll
    for (int o = 16; o > 0; o >>= 1)
        tr += __shfl_down_sync(0xffffffffu, tr, o);
    __shared__ float shr[8];
    if (lane == 0) shr[w] = tr;
    __syncthreads();
    if (t == 0) {
        float acc = 0.f;
#pragma unroll
        for (int i = 0; i < 8; ++i) acc += shr[i];
        g_partial[blockIdx.x] = acc;
    }
}

// ---------------------------------------------------------------------------
// Kernel 2: per-pixel matrix prep (fp32).
//   G = alpha*G/norm + (1-alpha)*0.25*I
//   A = 8*L*Ginv ; 8L ; d = sqrt(1.28)*rowsum(L)
//   (C = 0.64*G*Ginv == 0.64*I to fp32 rounding — folded into k_apply.)
// ---------------------------------------------------------------------------
__global__ __launch_bounds__(256) void k_prep(const float* __restrict__ t) {
    // reduce 512 trace partials redundantly per block
    __shared__ float sh_sum;
    {
        float v = g_partial[threadIdx.x] + g_partial[threadIdx.x + 256];
#pragma unroll
        for (int o = 16; o > 0; o >>= 1)
            v += __shfl_down_sync(0xffffffffu, v, o);
        __shared__ float sh[8];
        const int lane = threadIdx.x & 31;
        const int w    = threadIdx.x >> 5;
        if (lane == 0) sh[w] = v;
        __syncthreads();
        if (threadIdx.x == 0) {
            float acc = 0.f;
#pragma unroll
            for (int i = 0; i < 8; ++i) acc += sh[i];
            sh_sum = acc;
        }
        __syncthreads();
    }

    const int p = blockIdx.x * blockDim.x + threadIdx.x;
    const float t0 = __ldg(t);
    const float diag_mean = sh_sum / (65536.0f * 3.0f);
    const float norm  = (t0 == 1.0f) ? diag_mean * 4.0f : 1.0f;
    const float alpha = 0.5f * __expf(-4.5f * (1.0f - t0));
    const float sa = alpha / norm;
    const float diag_add = (1.0f - alpha) * 0.25f;

    const float a00 = g_G[0 * N_PIX + p] * sa + diag_add;
    const float a01 = g_G[1 * N_PIX + p] * sa;
    const float a02 = g_G[2 * N_PIX + p] * sa;
    const float a11 = g_G[3 * N_PIX + p] * sa + diag_add;
    const float a12 = g_G[4 * N_PIX + p] * sa;
    const float a22 = g_G[5 * N_PIX + p] * sa + diag_add;

    // adjugate inverse (fp32)
    const float c00 = a11 * a22 - a12 * a12;
    const float c01 = a02 * a12 - a01 * a22;
    const float c02 = a01 * a12 - a02 * a11;
    const float det = a00 * c00 + a01 * c01 + a02 * c02;
    const float id  = 1.0f / det;
    const float i00 = c00 * id;
    const float i01 = c01 * id;
    const float i02 = c02 * id;
    const float i11 = (a00 * a22 - a02 * a02) * id;
    const float i12 = (a01 * a02 - a00 * a12) * id;
    const float i22 = (a00 * a11 - a01 * a01) * id;

    // Cholesky (fp32)
    const float l00 = sqrtf(a00);
    const float il00 = 1.0f / l00;
    const float l10 = a01 * il00;
    const float l20 = a02 * il00;
    const float l11 = sqrtf(a11 - l10 * l10);
    const float l21 = (a12 - l20 * l10) / l11;
    const float l22 = sqrtf(a22 - l20 * l20 - l21 * l21);

    // A = 8 * L * Ginv
    const float A00 = 8.0f * (l00 * i00);
    const float A01 = 8.0f * (l00 * i01);
    const float A02 = 8.0f * (l00 * i02);
    const float A10 = 8.0f * (l10 * i00 + l11 * i01);
    const float A11 = 8.0f * (l10 * i01 + l11 * i11);
    const float A12 = 8.0f * (l10 * i02 + l11 * i12);
    const float A20 = 8.0f * (l20 * i00 + l21 * i01 + l22 * i02);
    const float A21 = 8.0f * (l20 * i01 + l21 * i11 + l22 * i12);
    const float A22 = 8.0f * (l20 * i02 + l21 * i12 + l22 * i22);

    const float bg = 1.1313708498984762f;  // sqrt(2*8*0.08)

    float* m = g_mats;
    m[ 0 * N_PIX + p] = A00; m[ 1 * N_PIX + p] = A01; m[ 2 * N_PIX + p] = A02;
    m[ 3 * N_PIX + p] = A10; m[ 4 * N_PIX + p] = A11; m[ 5 * N_PIX + p] = A12;
    m[ 6 * N_PIX + p] = A20; m[ 7 * N_PIX + p] = A21; m[ 8 * N_PIX + p] = A22;
    m[ 9 * N_PIX + p] = 8.0f * l00;
    m[10 * N_PIX + p] = 8.0f * l10;
    m[11 * N_PIX + p] = 8.0f * l11;
    m[12 * N_PIX + p] = 8.0f * l20;
    m[13 * N_PIX + p] = 8.0f * l21;
    m[14 * N_PIX + p] = 8.0f * l22;
    m[15 * N_PIX + p] = bg * l00;
    m[16 * N_PIX + p] = bg * (l10 + l11);
    m[17 * N_PIX + p] = bg * (l20 + l21 + l22);
}

// ---------------------------------------------------------------------------
// Kernel 3: streaming apply, float4 pixel-quads, 4 batches per thread.
//   drift_x = A r ; drift_r = -(8L) x - 0.64 r ; diffusion_r = d
// 18 float4 matrix regs (72) — fits 2 blocks/SM.
// ---------------------------------------------------------------------------
__global__ __launch_bounds__(256) void k_apply(const float4* __restrict__ u4,
                                               float4* __restrict__ out4) {
    const int idx = blockIdx.x * blockDim.x + threadIdx.x;  // 0..262143
    const int q   = idx & (N_Q - 1);
    const int bq  = idx >> 14;  // 0..15

    const float4* m4 = (const float4*)g_mats;
    const float4 A00 = __ldg(m4 +  0 * N_Q + q), A01 = __ldg(m4 +  1 * N_Q + q), A02 = __ldg(m4 +  2 * N_Q + q);
    const float4 A10 = __ldg(m4 +  3 * N_Q + q), A11 = __ldg(m4 +  4 * N_Q + q), A12 = __ldg(m4 +  5 * N_Q + q);
    const float4 A20 = __ldg(m4 +  6 * N_Q + q), A21 = __ldg(m4 +  7 * N_Q + q), A22 = __ldg(m4 +  8 * N_Q + q);
    const float4 L00 = __ldg(m4 +  9 * N_Q + q);
    const float4 L10 = __ldg(m4 + 10 * N_Q + q), L11 = __ldg(m4 + 11 * N_Q + q);
    const float4 L20 = __ldg(m4 + 12 * N_Q + q), L21 = __ldg(m4 + 13 * N_Q + q), L22 = __ldg(m4 + 14 * N_Q + q);
    const float4 D0  = __ldg(m4 + 15 * N_Q + q), D1 = __ldg(m4 + 16 * N_Q + q), D2 = __ldg(m4 + 17 * N_Q + q);

    const size_t diff_off = (size_t)BATCH * 6 * N_Q;  // 6291456 float4
    const float4 zero = make_float4(0.f, 0.f, 0.f, 0.f);
    const float cg = 0.64f;  // 0.64 * G * Ginv == 0.64 * I (fp32 rounding level)

#pragma unroll
    for (int i = 0; i < 4; ++i) {
        const int b = bq * 4 + i;
        const float4* ub = u4 + (size_t)b * (6 * N_Q) + q;
        const float4 x0 = __ldcs(ub);
        const float4 x1 = __ldcs(ub + N_Q);
        const float4 x2 = __ldcs(ub + 2 * N_Q);
        const float4 r0 = __ldcs(ub + 3 * N_Q);
        const float4 r1 = __ldcs(ub + 4 * N_Q);
        const float4 r2 = __ldcs(ub + 5 * N_Q);

        // drift_x = A r
        const float4 dx0 = f4fma(A02, r2, f4fma(A01, r1, f4mul(A00, r0)));
        const float4 dx1 = f4fma(A12, r2, f4fma(A11, r1, f4mul(A10, r0)));
        const float4 dx2 = f4fma(A22, r2, f4fma(A21, r1, f4mul(A20, r0)));
        // drift_r = -( (8L) x + 0.64 r )
        const float4 dr0 = f4neg(f4fma(L00, x0, f4scale(r0, cg)));
        const float4 dr1 = f4neg(f4fma(L11, x1, f4fma(L10, x0, f4scale(r1, cg))));
        const float4 dr2 = f4neg(f4fma(L22, x2, f4fma(L21, x1, f4fma(L20, x0, f4scale(r2, cg)))));

        float4* ob = out4 + (size_t)b * (6 * N_Q) + q;
        __stcs(ob + 0 * N_Q, dx0);
        __stcs(ob + 1 * N_Q, dx1);
        __stcs(ob + 2 * N_Q, dx2);
        __stcs(ob + 3 * N_Q, dr0);
        __stcs(ob + 4 * N_Q, dr1);
        __stcs(ob + 5 * N_Q, dr2);

        float4* db = ob + diff_off;
        __stcs(db + 0 * N_Q, zero);
        __stcs(db + 1 * N_Q, zero);
        __stcs(db + 2 * N_Q, zero);
        __stcs(db + 3 * N_Q, D0);
        __stcs(db + 4 * N_Q, D1);
        __stcs(db + 5 * N_Q, D2);
    }
}

// ---------------------------------------------------------------------------
extern "C" void kernel_launch(void* const* d_in, const int* in_sizes, int n_in,
                              void* d_out, int out_size) {
    const float4* u4 = (const float4*)d_in[0];   // [64, 6, 256, 256]
    const float4* s4 = (const float4*)d_in[1];   // [64, 3, 256, 256]
    const float*  t  = (const float*)d_in[2];    // [64]
    float4* out4 = (float4*)d_out;               // drift + diffusion

    k_covar<<<NBLK_COV, 256>>>(s4);
    k_prep<<<N_PIX / 256, 256>>>(t);
    k_apply<<<(N_Q * 16) / 256, 256>>>(u4, out4);
}